// round 1
// baseline (speedup 1.0000x reference)
#include <cuda_runtime.h>
#include <math.h>

#define B_     4
#define SQ_    4096
#define SKV_   1024
#define QDIM_  1024
#define CDIM_  768
#define HEADS_ 16
#define DHEAD_ 64
#define INNER_ 1024   // HEADS_*DHEAD_

// -------- scratch (static __device__ arrays: allocation-guard safe) --------
__device__ float g_Q [(size_t)B_ * SQ_  * INNER_];  // 64 MB
__device__ float g_K [(size_t)B_ * SKV_ * INNER_];  // 16 MB
__device__ float g_V [(size_t)B_ * SKV_ * INNER_];  // 16 MB
__device__ float g_AO[(size_t)B_ * SQ_  * INNER_];  // 64 MB

// ============================================================================
// SGEMM: C[M,N] = A[M,K] @ B[K,N] (+ bias), fp32.
// 128x128 block tile, BK=8, 256 threads, 8x8 register microtile.
// Requires M%128==0, N%128==0, K%8==0 (true for all 4 GEMMs here).
// ============================================================================
template<bool HAS_BIAS>
__global__ __launch_bounds__(256)
void sgemm_kernel(const float* __restrict__ A,
                  const float* __restrict__ Bm,
                  const float* __restrict__ bias,
                  float* __restrict__ C,
                  int M, int N, int K)
{
    const int BM = 128, BN = 128, BK = 8, TM = 8, TN = 8;
    __shared__ float As[BK][BM];
    __shared__ float Bs[BK][BN];

    const int t  = threadIdx.x;
    const int tc = t & 15;          // 0..15 -> N direction
    const int tr = t >> 4;          // 0..15 -> M direction
    const int bm = blockIdx.y * BM;
    const int bn = blockIdx.x * BN;

    float acc[TM][TN];
    #pragma unroll
    for (int i = 0; i < TM; i++)
        #pragma unroll
        for (int j = 0; j < TN; j++) acc[i][j] = 0.f;

    // cooperative load mapping
    const int aRow = t >> 1;            // 0..127
    const int aCol = (t & 1) * 4;       // 0 or 4
    const int bRow = t >> 5;            // 0..7
    const int bCol = (t & 31) * 4;      // 0..124

    const float* Aptr = A  + (size_t)bm * K;
    const float* Bptr = Bm + bn;

    for (int k0 = 0; k0 < K; k0 += BK) {
        float4 av = *(const float4*)(Aptr + (size_t)aRow * K + k0 + aCol);
        As[aCol + 0][aRow] = av.x;
        As[aCol + 1][aRow] = av.y;
        As[aCol + 2][aRow] = av.z;
        As[aCol + 3][aRow] = av.w;

        float4 bv = *(const float4*)(Bptr + (size_t)(k0 + bRow) * N + bCol);
        *(float4*)&Bs[bRow][bCol] = bv;

        __syncthreads();

        #pragma unroll
        for (int kk = 0; kk < BK; kk++) {
            float ra[TM], rb[TN];
            #pragma unroll
            for (int i = 0; i < TM; i++) ra[i] = As[kk][tr * TM + i];
            #pragma unroll
            for (int j = 0; j < TN; j++) rb[j] = Bs[kk][tc * TN + j];
            #pragma unroll
            for (int i = 0; i < TM; i++)
                #pragma unroll
                for (int j = 0; j < TN; j++)
                    acc[i][j] = fmaf(ra[i], rb[j], acc[i][j]);
        }
        __syncthreads();
    }

    #pragma unroll
    for (int i = 0; i < TM; i++) {
        const int row = bm + tr * TM + i;
        #pragma unroll
        for (int j = 0; j < TN; j += 4) {
            const int col = bn + tc * TN + j;
            float4 v;
            v.x = acc[i][j + 0];
            v.y = acc[i][j + 1];
            v.z = acc[i][j + 2];
            v.w = acc[i][j + 3];
            if (HAS_BIAS) {
                v.x += bias[col + 0];
                v.y += bias[col + 1];
                v.z += bias[col + 2];
                v.w += bias[col + 3];
            }
            *(float4*)(C + (size_t)row * N + col) = v;
        }
    }
}

// ============================================================================
// Flash attention, fp32. One block = one (b,h) and 64 q rows.
// KV streamed in 64-row tiles with online softmax.
// 256 threads; 16x16 thread grid, 4x4 microtiles for both GEMMs.
// Q/K/V layouts: [b, s, h*64 + d] (row stride INNER_).
// ============================================================================
__global__ __launch_bounds__(256)
void attn_kernel(const float* __restrict__ Qg,
                 const float* __restrict__ Kg,
                 const float* __restrict__ Vg,
                 float* __restrict__ Og)
{
    extern __shared__ float sm[];
    float* Qs   = sm;               // [64][65]  transposed: Qs[d][r]
    float* Ks   = Qs + 64 * 65;     // [64][65]  transposed: Ks[d][c]
    float* Vs   = Ks + 64 * 65;     // [64][64]  natural:    Vs[kv][d]
    float* Ps   = Vs + 64 * 64;     // [64][65]  transposed: Ps[kv][r]
    float* rowc = Ps + 64 * 65;     // [64] per-row correction factor
    float* rowl = rowc + 64;        // [64] final softmax denominators

    const int t  = threadIdx.x;
    const int tc = t & 15;
    const int tr = t >> 4;
    const int bh = blockIdx.y;
    const int b  = bh >> 4;
    const int h  = bh & 15;
    const int q0 = blockIdx.x * 64;

    const float scale = 0.125f;     // DHEAD^-0.5 = 1/8

    const size_t qbase = ((size_t)(b * SQ_) + q0) * INNER_ + h * DHEAD_;
    const size_t kbase = ((size_t)(b * SKV_)) * INNER_ + h * DHEAD_;

    // load Q tile, transposed, padded stride 65 (conflict-free STS)
    for (int idx = t; idx < 64 * 64; idx += 256) {
        const int r = idx >> 6, d = idx & 63;
        Qs[d * 65 + r] = Qg[qbase + (size_t)r * INNER_ + d];
    }

    float o[4][4];
    #pragma unroll
    for (int i = 0; i < 4; i++)
        #pragma unroll
        for (int j = 0; j < 4; j++) o[i][j] = 0.f;

    float m_run = -1e30f, l_run = 0.f;   // live in threads t<64 (one per q row)

    for (int kt = 0; kt < SKV_ / 64; kt++) {
        __syncthreads();   // prev iteration fully consumed Ks/Vs/Ps

        const size_t kb = kbase + (size_t)kt * 64 * INNER_;
        for (int idx = t; idx < 64 * 64; idx += 256) {
            const int r = idx >> 6, d = idx & 63;
            Ks[d * 65 + r] = Kg[kb + (size_t)r * INNER_ + d];
            Vs[idx]        = Vg[kb + (size_t)r * INNER_ + d];
        }
        __syncthreads();

        // S = Q @ K^T  (64x64x64)
        float s[4][4];
        #pragma unroll
        for (int i = 0; i < 4; i++)
            #pragma unroll
            for (int j = 0; j < 4; j++) s[i][j] = 0.f;

        #pragma unroll 8
        for (int d = 0; d < 64; d++) {
            float qa[4], ka[4];
            #pragma unroll
            for (int i = 0; i < 4; i++) qa[i] = Qs[d * 65 + tr * 4 + i];
            #pragma unroll
            for (int j = 0; j < 4; j++) ka[j] = Ks[d * 65 + tc * 4 + j];
            #pragma unroll
            for (int i = 0; i < 4; i++)
                #pragma unroll
                for (int j = 0; j < 4; j++)
                    s[i][j] = fmaf(qa[i], ka[j], s[i][j]);
        }
        // write P^T (scaled logits) to shared
        #pragma unroll
        for (int j = 0; j < 4; j++)
            #pragma unroll
            for (int i = 0; i < 4; i++)
                Ps[(tc * 4 + j) * 65 + tr * 4 + i] = s[i][j] * scale;
        __syncthreads();

        // online softmax: thread t<64 owns q-row t; reads Ps column (contiguous across threads)
        if (t < 64) {
            float mt = -1e30f;
            #pragma unroll 8
            for (int j = 0; j < 64; j++) mt = fmaxf(mt, Ps[j * 65 + t]);
            const float mnew = fmaxf(m_run, mt);
            const float corr = __expf(m_run - mnew);   // first tile: exp(-huge)=0
            float sum = 0.f;
            #pragma unroll 8
            for (int j = 0; j < 64; j++) {
                const float p = __expf(Ps[j * 65 + t] - mnew);
                Ps[j * 65 + t] = p;
                sum += p;
            }
            l_run = l_run * corr + sum;
            m_run = mnew;
            rowc[t] = corr;
        }
        __syncthreads();

        // rescale accumulators, then O += P @ V  (64x64x64)
        float cr[4];
        #pragma unroll
        for (int i = 0; i < 4; i++) cr[i] = rowc[tr * 4 + i];
        #pragma unroll
        for (int i = 0; i < 4; i++)
            #pragma unroll
            for (int j = 0; j < 4; j++) o[i][j] *= cr[i];

        #pragma unroll 8
        for (int kv = 0; kv < 64; kv++) {
            float pa[4], va[4];
            #pragma unroll
            for (int i = 0; i < 4; i++) pa[i] = Ps[kv * 65 + tr * 4 + i];
            #pragma unroll
            for (int j = 0; j < 4; j++) va[j] = Vs[kv * 64 + tc * 4 + j];
            #pragma unroll
            for (int i = 0; i < 4; i++)
                #pragma unroll
                for (int j = 0; j < 4; j++)
                    o[i][j] = fmaf(pa[i], va[j], o[i][j]);
        }
    }

    if (t < 64) rowl[t] = l_run;
    __syncthreads();

    #pragma unroll
    for (int i = 0; i < 4; i++) {
        const float inv = 1.0f / rowl[tr * 4 + i];
        #pragma unroll
        for (int j = 0; j < 4; j++)
            Og[qbase + (size_t)(tr * 4 + i) * INNER_ + tc * 4 + j] = o[i][j] * inv;
    }
}

// ============================================================================
// launch
// ============================================================================
extern "C" void kernel_launch(void* const* d_in, const int* in_sizes, int n_in,
                              void* d_out, int out_size)
{
    const float* x   = (const float*)d_in[0];
    const float* ctx = (const float*)d_in[1];
    const float* Wq  = (const float*)d_in[2];
    const float* Wk  = (const float*)d_in[3];
    const float* Wv  = (const float*)d_in[4];
    const float* Wo  = (const float*)d_in[5];
    const float* bo  = (const float*)d_in[6];
    float* out = (float*)d_out;

    float *Qb, *Kb, *Vb, *AOb;
    cudaGetSymbolAddress((void**)&Qb,  g_Q);
    cudaGetSymbolAddress((void**)&Kb,  g_K);
    cudaGetSymbolAddress((void**)&Vb,  g_V);
    cudaGetSymbolAddress((void**)&AOb, g_AO);

    const dim3 blk(256);

    // Q = x @ Wq            [16384,1024] x [1024,1024]
    sgemm_kernel<false><<<dim3(INNER_ / 128, (B_ * SQ_) / 128), blk>>>(
        x, Wq, nullptr, Qb, B_ * SQ_, INNER_, QDIM_);
    // K = ctx @ Wk          [4096,768] x [768,1024]
    sgemm_kernel<false><<<dim3(INNER_ / 128, (B_ * SKV_) / 128), blk>>>(
        ctx, Wk, nullptr, Kb, B_ * SKV_, INNER_, CDIM_);
    // V = ctx @ Wv
    sgemm_kernel<false><<<dim3(INNER_ / 128, (B_ * SKV_) / 128), blk>>>(
        ctx, Wv, nullptr, Vb, B_ * SKV_, INNER_, CDIM_);

    // flash attention
    const int smem_bytes = (64 * 65 * 3 + 64 * 64 + 128) * (int)sizeof(float); // 66816
    cudaFuncSetAttribute(attn_kernel,
                         cudaFuncAttributeMaxDynamicSharedMemorySize, smem_bytes);
    attn_kernel<<<dim3(SQ_ / 64, B_ * HEADS_), blk, smem_bytes>>>(Qb, Kb, Vb, AOb);

    // out = AO @ Wo + bo    [16384,1024] x [1024,1024]
    sgemm_kernel<true><<<dim3(QDIM_ / 128, (B_ * SQ_) / 128), blk>>>(
        AOb, Wo, bo, out, B_ * SQ_, QDIM_, INNER_);
}

// round 3
// speedup vs baseline: 1.3458x; 1.3458x over previous
#include <cuda_runtime.h>
#include <cuda_bf16.h>
#include <math.h>
#include <stdint.h>

#define B_     4
#define SQ_    4096
#define SKV_   1024
#define QDIM_  1024
#define CDIM_  768
#define HEADS_ 16
#define DHEAD_ 64
#define INNER_ 1024   // HEADS_*DHEAD_

// ---------------- scratch (__device__ globals: allocation-guard safe) -------
__device__ float g_Q [(size_t)B_ * SQ_  * INNER_];
__device__ float g_K [(size_t)B_ * SKV_ * INNER_];
__device__ float g_V [(size_t)B_ * SKV_ * INNER_];
__device__ float g_AO[(size_t)B_ * SQ_  * INNER_];

__device__ __nv_bfloat16 g_xh [(size_t)B_ * SQ_  * QDIM_];
__device__ __nv_bfloat16 g_xl [(size_t)B_ * SQ_  * QDIM_];
__device__ __nv_bfloat16 g_ch [(size_t)B_ * SKV_ * CDIM_];
__device__ __nv_bfloat16 g_cl [(size_t)B_ * SKV_ * CDIM_];
__device__ __nv_bfloat16 g_aoh[(size_t)B_ * SQ_  * INNER_];
__device__ __nv_bfloat16 g_aol[(size_t)B_ * SQ_  * INNER_];
// transposed weights [N,K] hi/lo
__device__ __nv_bfloat16 g_Wqh[INNER_ * QDIM_], g_Wql[INNER_ * QDIM_];
__device__ __nv_bfloat16 g_Wkh[INNER_ * CDIM_], g_Wkl[INNER_ * CDIM_];
__device__ __nv_bfloat16 g_Wvh[INNER_ * CDIM_], g_Wvl[INNER_ * CDIM_];
__device__ __nv_bfloat16 g_Woh[QDIM_ * INNER_], g_Wol[QDIM_ * INNER_];

// ---------------- PTX helpers (all plain compute_103-legal) -----------------
__device__ __forceinline__ uint32_t smem_u32(const void* p) {
    uint32_t a;
    asm("{ .reg .u64 t; cvta.to.shared.u64 t, %1; cvt.u32.u64 %0, t; }"
        : "=r"(a) : "l"(p));
    return a;
}
__device__ __forceinline__ void cp_async16(uint32_t dst, const void* src) {
    asm volatile("cp.async.cg.shared.global [%0], [%1], 16;"
                 :: "r"(dst), "l"(src) : "memory");
}
__device__ __forceinline__ void cp_commit() {
    asm volatile("cp.async.commit_group;" ::: "memory");
}
__device__ __forceinline__ void cp_wait2() {
    asm volatile("cp.async.wait_group 2;" ::: "memory");
}
__device__ __forceinline__ void ldmatrix_x4(uint32_t& r0, uint32_t& r1,
                                            uint32_t& r2, uint32_t& r3,
                                            uint32_t addr) {
    asm volatile("ldmatrix.sync.aligned.m8n8.x4.shared.b16 {%0,%1,%2,%3}, [%4];"
                 : "=r"(r0), "=r"(r1), "=r"(r2), "=r"(r3) : "r"(addr));
}
__device__ __forceinline__ void mma_bf16(float* c, const uint32_t* a,
                                         const uint32_t* b) {
    asm volatile(
        "mma.sync.aligned.m16n8k16.row.col.f32.bf16.bf16.f32 "
        "{%0,%1,%2,%3}, {%4,%5,%6,%7}, {%8,%9}, {%0,%1,%2,%3};"
        : "+f"(c[0]), "+f"(c[1]), "+f"(c[2]), "+f"(c[3])
        : "r"(a[0]), "r"(a[1]), "r"(a[2]), "r"(a[3]), "r"(b[0]), "r"(b[1]));
}

// ============================================================================
// split fp32 -> (hi, lo) bf16, elementwise. n % 4 == 0.
// ============================================================================
__global__ __launch_bounds__(256)
void split_kernel(const float* __restrict__ in,
                  __nv_bfloat16* __restrict__ hi,
                  __nv_bfloat16* __restrict__ lo, int n)
{
    int i = (blockIdx.x * 256 + threadIdx.x) * 4;
    if (i >= n) return;
    float4 v = *(const float4*)(in + i);
    __nv_bfloat16 h0 = __float2bfloat16_rn(v.x);
    __nv_bfloat16 h1 = __float2bfloat16_rn(v.y);
    __nv_bfloat16 h2 = __float2bfloat16_rn(v.z);
    __nv_bfloat16 h3 = __float2bfloat16_rn(v.w);
    __nv_bfloat16 l0 = __float2bfloat16_rn(v.x - __bfloat162float(h0));
    __nv_bfloat16 l1 = __float2bfloat16_rn(v.y - __bfloat162float(h1));
    __nv_bfloat16 l2 = __float2bfloat16_rn(v.z - __bfloat162float(h2));
    __nv_bfloat16 l3 = __float2bfloat16_rn(v.w - __bfloat162float(h3));
    ((__nv_bfloat162*)(hi + i))[0] = __nv_bfloat162(h0, h1);
    ((__nv_bfloat162*)(hi + i))[1] = __nv_bfloat162(h2, h3);
    ((__nv_bfloat162*)(lo + i))[0] = __nv_bfloat162(l0, l1);
    ((__nv_bfloat162*)(lo + i))[1] = __nv_bfloat162(l2, l3);
}

// ============================================================================
// transpose + split: W fp32 [K,N] -> hi/lo bf16 [N,K].  K,N % 32 == 0.
// ============================================================================
__global__ __launch_bounds__(256)
void tsplit_kernel(const float* __restrict__ W,
                   __nv_bfloat16* __restrict__ ht,
                   __nv_bfloat16* __restrict__ lt, int K, int N)
{
    __shared__ float tile[32][33];
    const int k0 = blockIdx.y * 32, n0 = blockIdx.x * 32;
    const int tx = threadIdx.x & 31, ty = threadIdx.x >> 5; // ty 0..7
    for (int r = ty; r < 32; r += 8)
        tile[r][tx] = W[(size_t)(k0 + r) * N + n0 + tx];
    __syncthreads();
    for (int r = ty; r < 32; r += 8) {
        float v = tile[tx][r];                  // = W[k0+tx][n0+r]
        __nv_bfloat16 h = __float2bfloat16_rn(v);
        __nv_bfloat16 l = __float2bfloat16_rn(v - __bfloat162float(h));
        ht[(size_t)(n0 + r) * K + k0 + tx] = h;
        lt[(size_t)(n0 + r) * K + k0 + tx] = l;
    }
}

// ============================================================================
// HMMA GEMM: C[M,N] = (Ah+Al)[M,K] @ (Bh+Bl)^T  (+ bias), fp32 out.
//   A row-major [M,K] bf16 hi/lo.  B row-major [N,K] bf16 hi/lo (pre-transposed).
//   3-term split folded into a virtual-K loop over segments
//   (Ah,Bh), (Al,Bh), (Ah,Bl).
//   BM=BN=128, BK=32, 4-stage cp.async, 256 threads, 8 warps (4m x 2n),
//   warp tile 32x64, mma.sync m16n8k16 bf16.
// ============================================================================
#define MM_BM 128
#define MM_BN 128
#define MM_BK 32
#define MM_ROWB 80                    // padded row bytes (32 bf16 = 64B + 16B pad)
#define MM_AB  (128 * MM_ROWB)        // 10240 bytes
#define MM_STAGE (2 * MM_AB)          // A + B per stage = 20480
#define MM_SMEM (4 * MM_STAGE)        // 81920

template<bool HAS_BIAS>
__global__ __launch_bounds__(256)
void gemm_mma(const __nv_bfloat16* __restrict__ Ah,
              const __nv_bfloat16* __restrict__ Al,
              const __nv_bfloat16* __restrict__ Bh,
              const __nv_bfloat16* __restrict__ Bl,
              const float* __restrict__ bias,
              float* __restrict__ C,
              int M, int N, int K)
{
    extern __shared__ __align__(16) char smem_raw[];
    const uint32_t sbase = smem_u32(smem_raw);

    const int tid  = threadIdx.x;
    const int wid  = tid >> 5, lane = tid & 31;
    const int wm   = wid >> 1, wn = wid & 1;       // 4 x 2 warp grid
    const int m0   = blockIdx.y * MM_BM;
    const int n0   = blockIdx.x * MM_BN;

    const __nv_bfloat16* Asegs[3] = {Ah, Al, Ah};
    const __nv_bfloat16* Bsegs[3] = {Bh, Bh, Bl};
    const int kiters = K / MM_BK;
    const int T = 3 * kiters;

    // per-thread cooperative-load coords: 2 chunks of A + 2 of B per stage
    auto load_stage = [&](int t, int s) {
        const int seg = t / kiters;
        const int kk  = (t - seg * kiters) * MM_BK;
        const __nv_bfloat16* Ap = Asegs[seg];
        const __nv_bfloat16* Bp = Bsegs[seg];
        const uint32_t sa = sbase + (uint32_t)s * MM_STAGE;
        const uint32_t sb = sa + MM_AB;
        #pragma unroll
        for (int i = 0; i < 2; i++) {
            const int idx = i * 256 + tid;       // 0..511
            const int r = idx >> 2, c = idx & 3;
            cp_async16(sa + r * MM_ROWB + c * 16,
                       Ap + (size_t)(m0 + r) * K + kk + c * 8);
            cp_async16(sb + r * MM_ROWB + c * 16,
                       Bp + (size_t)(n0 + r) * K + kk + c * 8);
        }
        cp_commit();
    };

    float acc[2][8][4];
    #pragma unroll
    for (int mi = 0; mi < 2; mi++)
        #pragma unroll
        for (int nj = 0; nj < 8; nj++)
            #pragma unroll
            for (int q = 0; q < 4; q++) acc[mi][nj][q] = 0.f;

    // prologue: 3 stages in flight
    load_stage(0, 0);
    load_stage(1, 1);
    load_stage(2, 2);

    // precomputed ldmatrix lane-address components
    const uint32_t aRow = (uint32_t)(wm * 32 + (lane & 15));      // + mi*16
    const uint32_t aKof = ((lane >> 4) << 4);                     // 0 / 16
    const uint32_t bRow = (uint32_t)(wn * 64 + ((lane >> 4) & 1) * 8 + (lane & 7)); // + nj*8
    const uint32_t bKof = (((lane >> 3) & 1) << 4);

    for (int t = 0; t < T; t++) {
        const int s = t & 3;
        cp_wait2();
        __syncthreads();

        const uint32_t sa = sbase + (uint32_t)s * MM_STAGE;
        const uint32_t sb = sa + MM_AB;

        #pragma unroll
        for (int ks = 0; ks < 2; ks++) {
            uint32_t a[2][4], b[8][2];
            #pragma unroll
            for (int mi = 0; mi < 2; mi++) {
                const uint32_t addr =
                    sa + (aRow + mi * 16) * MM_ROWB + ks * 32 + aKof;
                ldmatrix_x4(a[mi][0], a[mi][1], a[mi][2], a[mi][3], addr);
            }
            #pragma unroll
            for (int nj = 0; nj < 8; nj += 2) {
                const uint32_t addr =
                    sb + (bRow + nj * 8) * MM_ROWB + ks * 32 + bKof;
                ldmatrix_x4(b[nj][0], b[nj][1], b[nj + 1][0], b[nj + 1][1], addr);
            }
            #pragma unroll
            for (int mi = 0; mi < 2; mi++)
                #pragma unroll
                for (int nj = 0; nj < 8; nj++)
                    mma_bf16(acc[mi][nj], a[mi], b[nj]);
        }

        __syncthreads();
        if (t + 3 < T) load_stage(t + 3, (t + 3) & 3);
        else           cp_commit();    // keep group count advancing for wait_group
    }

    // epilogue: write fp32 (+bias)
    #pragma unroll
    for (int mi = 0; mi < 2; mi++) {
        const int row = m0 + wm * 32 + mi * 16 + (lane >> 2);
        #pragma unroll
        for (int nj = 0; nj < 8; nj++) {
            const int col = n0 + wn * 64 + nj * 8 + 2 * (lane & 3);
            float2 v0 = make_float2(acc[mi][nj][0], acc[mi][nj][1]);
            float2 v1 = make_float2(acc[mi][nj][2], acc[mi][nj][3]);
            if (HAS_BIAS) {
                const float b0 = bias[col], b1 = bias[col + 1];
                v0.x += b0; v0.y += b1;
                v1.x += b0; v1.y += b1;
            }
            *(float2*)(C + (size_t)row * N + col)       = v0;
            *(float2*)(C + (size_t)(row + 8) * N + col) = v1;
        }
    }
}

// ============================================================================
// Flash attention, fp32 (unchanged — validated round 1).
// ============================================================================
__global__ __launch_bounds__(256)
void attn_kernel(const float* __restrict__ Qg,
                 const float* __restrict__ Kg,
                 const float* __restrict__ Vg,
                 float* __restrict__ Og)
{
    extern __shared__ float sm[];
    float* Qs   = sm;
    float* Ks   = Qs + 64 * 65;
    float* Vs   = Ks + 64 * 65;
    float* Ps   = Vs + 64 * 64;
    float* rowc = Ps + 64 * 65;
    float* rowl = rowc + 64;

    const int t  = threadIdx.x;
    const int tc = t & 15;
    const int tr = t >> 4;
    const int bh = blockIdx.y;
    const int b  = bh >> 4;
    const int h  = bh & 15;
    const int q0 = blockIdx.x * 64;

    const float scale = 0.125f;

    const size_t qbase = ((size_t)(b * SQ_) + q0) * INNER_ + h * DHEAD_;
    const size_t kbase = ((size_t)(b * SKV_)) * INNER_ + h * DHEAD_;

    for (int idx = t; idx < 64 * 64; idx += 256) {
        const int r = idx >> 6, d = idx & 63;
        Qs[d * 65 + r] = Qg[qbase + (size_t)r * INNER_ + d];
    }

    float o[4][4];
    #pragma unroll
    for (int i = 0; i < 4; i++)
        #pragma unroll
        for (int j = 0; j < 4; j++) o[i][j] = 0.f;

    float m_run = -1e30f, l_run = 0.f;

    for (int kt = 0; kt < SKV_ / 64; kt++) {
        __syncthreads();

        const size_t kb = kbase + (size_t)kt * 64 * INNER_;
        for (int idx = t; idx < 64 * 64; idx += 256) {
            const int r = idx >> 6, d = idx & 63;
            Ks[d * 65 + r] = Kg[kb + (size_t)r * INNER_ + d];
            Vs[idx]        = Vg[kb + (size_t)r * INNER_ + d];
        }
        __syncthreads();

        float s[4][4];
        #pragma unroll
        for (int i = 0; i < 4; i++)
            #pragma unroll
            for (int j = 0; j < 4; j++) s[i][j] = 0.f;

        #pragma unroll 8
        for (int d = 0; d < 64; d++) {
            float qa[4], ka[4];
            #pragma unroll
            for (int i = 0; i < 4; i++) qa[i] = Qs[d * 65 + tr * 4 + i];
            #pragma unroll
            for (int j = 0; j < 4; j++) ka[j] = Ks[d * 65 + tc * 4 + j];
            #pragma unroll
            for (int i = 0; i < 4; i++)
                #pragma unroll
                for (int j = 0; j < 4; j++)
                    s[i][j] = fmaf(qa[i], ka[j], s[i][j]);
        }
        #pragma unroll
        for (int j = 0; j < 4; j++)
            #pragma unroll
            for (int i = 0; i < 4; i++)
                Ps[(tc * 4 + j) * 65 + tr * 4 + i] = s[i][j] * scale;
        __syncthreads();

        if (t < 64) {
            float mt = -1e30f;
            #pragma unroll 8
            for (int j = 0; j < 64; j++) mt = fmaxf(mt, Ps[j * 65 + t]);
            const float mnew = fmaxf(m_run, mt);
            const float corr = __expf(m_run - mnew);
            float sum = 0.f;
            #pragma unroll 8
            for (int j = 0; j < 64; j++) {
                const float p = __expf(Ps[j * 65 + t] - mnew);
                Ps[j * 65 + t] = p;
                sum += p;
            }
            l_run = l_run * corr + sum;
            m_run = mnew;
            rowc[t] = corr;
        }
        __syncthreads();

        float cr[4];
        #pragma unroll
        for (int i = 0; i < 4; i++) cr[i] = rowc[tr * 4 + i];
        #pragma unroll
        for (int i = 0; i < 4; i++)
            #pragma unroll
            for (int j = 0; j < 4; j++) o[i][j] *= cr[i];

        #pragma unroll 8
        for (int kv = 0; kv < 64; kv++) {
            float pa[4], va[4];
            #pragma unroll
            for (int i = 0; i < 4; i++) pa[i] = Ps[kv * 65 + tr * 4 + i];
            #pragma unroll
            for (int j = 0; j < 4; j++) va[j] = Vs[kv * 64 + tc * 4 + j];
            #pragma unroll
            for (int i = 0; i < 4; i++)
                #pragma unroll
                for (int j = 0; j < 4; j++)
                    o[i][j] = fmaf(pa[i], va[j], o[i][j]);
        }
    }

    if (t < 64) rowl[t] = l_run;
    __syncthreads();

    #pragma unroll
    for (int i = 0; i < 4; i++) {
        const float inv = 1.0f / rowl[tr * 4 + i];
        #pragma unroll
        for (int j = 0; j < 4; j++)
            Og[qbase + (size_t)(tr * 4 + i) * INNER_ + tc * 4 + j] = o[i][j] * inv;
    }
}

// ============================================================================
// launch
// ============================================================================
extern "C" void kernel_launch(void* const* d_in, const int* in_sizes, int n_in,
                              void* d_out, int out_size)
{
    const float* x   = (const float*)d_in[0];
    const float* ctx = (const float*)d_in[1];
    const float* Wq  = (const float*)d_in[2];
    const float* Wk  = (const float*)d_in[3];
    const float* Wv  = (const float*)d_in[4];
    const float* Wo  = (const float*)d_in[5];
    const float* bo  = (const float*)d_in[6];
    float* out = (float*)d_out;

    float *Qb, *Kb, *Vb, *AOb;
    cudaGetSymbolAddress((void**)&Qb,  g_Q);
    cudaGetSymbolAddress((void**)&Kb,  g_K);
    cudaGetSymbolAddress((void**)&Vb,  g_V);
    cudaGetSymbolAddress((void**)&AOb, g_AO);
    __nv_bfloat16 *xh, *xl, *ch, *cl, *aoh, *aol;
    __nv_bfloat16 *wqh, *wql, *wkh, *wkl, *wvh, *wvl, *woh, *wol;
    cudaGetSymbolAddress((void**)&xh,  g_xh);   cudaGetSymbolAddress((void**)&xl,  g_xl);
    cudaGetSymbolAddress((void**)&ch,  g_ch);   cudaGetSymbolAddress((void**)&cl,  g_cl);
    cudaGetSymbolAddress((void**)&aoh, g_aoh);  cudaGetSymbolAddress((void**)&aol, g_aol);
    cudaGetSymbolAddress((void**)&wqh, g_Wqh);  cudaGetSymbolAddress((void**)&wql, g_Wql);
    cudaGetSymbolAddress((void**)&wkh, g_Wkh);  cudaGetSymbolAddress((void**)&wkl, g_Wkl);
    cudaGetSymbolAddress((void**)&wvh, g_Wvh);  cudaGetSymbolAddress((void**)&wvl, g_Wvl);
    cudaGetSymbolAddress((void**)&woh, g_Woh);  cudaGetSymbolAddress((void**)&wol, g_Wol);

    const int nx  = B_ * SQ_  * QDIM_;
    const int nc  = B_ * SKV_ * CDIM_;
    const int nao = B_ * SQ_  * INNER_;

    // splits + weight transposes
    split_kernel<<<nx  / 1024, 256>>>(x,   xh, xl, nx);
    split_kernel<<<nc  / 1024, 256>>>(ctx, ch, cl, nc);
    tsplit_kernel<<<dim3(INNER_ / 32, QDIM_ / 32), 256>>>(Wq, wqh, wql, QDIM_, INNER_);
    tsplit_kernel<<<dim3(INNER_ / 32, CDIM_ / 32), 256>>>(Wk, wkh, wkl, CDIM_, INNER_);
    tsplit_kernel<<<dim3(INNER_ / 32, CDIM_ / 32), 256>>>(Wv, wvh, wvl, CDIM_, INNER_);
    tsplit_kernel<<<dim3(QDIM_  / 32, INNER_ / 32), 256>>>(Wo, woh, wol, INNER_, QDIM_);

    cudaFuncSetAttribute(gemm_mma<false>,
                         cudaFuncAttributeMaxDynamicSharedMemorySize, MM_SMEM);
    cudaFuncSetAttribute(gemm_mma<true>,
                         cudaFuncAttributeMaxDynamicSharedMemorySize, MM_SMEM);

    // Q = x@Wq, K = ctx@Wk, V = ctx@Wv
    gemm_mma<false><<<dim3(INNER_ / MM_BN, (B_ * SQ_)  / MM_BM), 256, MM_SMEM>>>(
        xh, xl, wqh, wql, nullptr, Qb, B_ * SQ_,  INNER_, QDIM_);
    gemm_mma<false><<<dim3(INNER_ / MM_BN, (B_ * SKV_) / MM_BM), 256, MM_SMEM>>>(
        ch, cl, wkh, wkl, nullptr, Kb, B_ * SKV_, INNER_, CDIM_);
    gemm_mma<false><<<dim3(INNER_ / MM_BN, (B_ * SKV_) / MM_BM), 256, MM_SMEM>>>(
        ch, cl, wvh, wvl, nullptr, Vb, B_ * SKV_, INNER_, CDIM_);

    // attention (fp32, unchanged)
    const int smem_bytes = (64 * 65 * 3 + 64 * 64 + 128) * (int)sizeof(float);
    cudaFuncSetAttribute(attn_kernel,
                         cudaFuncAttributeMaxDynamicSharedMemorySize, smem_bytes);
    attn_kernel<<<dim3(SQ_ / 64, B_ * HEADS_), 256, smem_bytes>>>(Qb, Kb, Vb, AOb);

    // out = AO @ Wo + bo
    split_kernel<<<nao / 1024, 256>>>(AOb, aoh, aol, nao);
    gemm_mma<true><<<dim3(QDIM_ / MM_BN, (B_ * SQ_) / MM_BM), 256, MM_SMEM>>>(
        aoh, aol, woh, wol, bo, out, B_ * SQ_, QDIM_, INNER_);
}

// round 4
// speedup vs baseline: 2.6315x; 1.9554x over previous
#include <cuda_runtime.h>
#include <cuda_bf16.h>
#include <math.h>
#include <stdint.h>
#include <string.h>

#define B_     4
#define SQ_    4096
#define SKV_   1024
#define QDIM_  1024
#define CDIM_  768
#define HEADS_ 16
#define DHEAD_ 64
#define INNER_ 1024   // HEADS_*DHEAD_
#define BH_    (B_ * HEADS_)

// ---------------- scratch (__device__ globals: allocation-guard safe) -------
__device__ __nv_bfloat16 g_xh [(size_t)B_ * SQ_  * QDIM_];
__device__ __nv_bfloat16 g_xl [(size_t)B_ * SQ_  * QDIM_];
__device__ __nv_bfloat16 g_ch [(size_t)B_ * SKV_ * CDIM_];
__device__ __nv_bfloat16 g_cl [(size_t)B_ * SKV_ * CDIM_];
// projections out (bf16 hi/lo, layout [b, s, h*64+d])
__device__ __nv_bfloat16 g_Qh [(size_t)B_ * SQ_  * INNER_];
__device__ __nv_bfloat16 g_Ql [(size_t)B_ * SQ_  * INNER_];
__device__ __nv_bfloat16 g_Kh [(size_t)B_ * SKV_ * INNER_];
__device__ __nv_bfloat16 g_Kl [(size_t)B_ * SKV_ * INNER_];
__device__ __nv_bfloat16 g_Vh [(size_t)B_ * SKV_ * INNER_];
__device__ __nv_bfloat16 g_Vl [(size_t)B_ * SKV_ * INNER_];
// V transposed: [(b*16+h)*64 + d][skv]
__device__ __nv_bfloat16 g_Vth[(size_t)BH_ * DHEAD_ * SKV_];
__device__ __nv_bfloat16 g_Vtl[(size_t)BH_ * DHEAD_ * SKV_];
// attention out (bf16 hi/lo, layout [b, s, inner])
__device__ __nv_bfloat16 g_aoh[(size_t)B_ * SQ_  * INNER_];
__device__ __nv_bfloat16 g_aol[(size_t)B_ * SQ_  * INNER_];
// transposed weights [N,K] hi/lo
__device__ __nv_bfloat16 g_Wqh[INNER_ * QDIM_], g_Wql[INNER_ * QDIM_];
__device__ __nv_bfloat16 g_Wkh[INNER_ * CDIM_], g_Wkl[INNER_ * CDIM_];
__device__ __nv_bfloat16 g_Wvh[INNER_ * CDIM_], g_Wvl[INNER_ * CDIM_];
__device__ __nv_bfloat16 g_Woh[QDIM_ * INNER_], g_Wol[QDIM_ * INNER_];

// ---------------- PTX helpers (plain compute_103-legal) ---------------------
__device__ __forceinline__ uint32_t smem_u32(const void* p) {
    uint32_t a;
    asm("{ .reg .u64 t; cvta.to.shared.u64 t, %1; cvt.u32.u64 %0, t; }"
        : "=r"(a) : "l"(p));
    return a;
}
__device__ __forceinline__ void cp_async16(uint32_t dst, const void* src) {
    asm volatile("cp.async.cg.shared.global [%0], [%1], 16;"
                 :: "r"(dst), "l"(src) : "memory");
}
__device__ __forceinline__ void cp_commit() {
    asm volatile("cp.async.commit_group;" ::: "memory");
}
template<int N>
__device__ __forceinline__ void cp_wait() {
    asm volatile("cp.async.wait_group %0;" :: "n"(N) : "memory");
}
__device__ __forceinline__ void ldmatrix_x4(uint32_t& r0, uint32_t& r1,
                                            uint32_t& r2, uint32_t& r3,
                                            uint32_t addr) {
    asm volatile("ldmatrix.sync.aligned.m8n8.x4.shared.b16 {%0,%1,%2,%3}, [%4];"
                 : "=r"(r0), "=r"(r1), "=r"(r2), "=r"(r3) : "r"(addr));
}
__device__ __forceinline__ void mma_bf16(float* c, const uint32_t* a,
                                         const uint32_t* b) {
    asm volatile(
        "mma.sync.aligned.m16n8k16.row.col.f32.bf16.bf16.f32 "
        "{%0,%1,%2,%3}, {%4,%5,%6,%7}, {%8,%9}, {%0,%1,%2,%3};"
        : "+f"(c[0]), "+f"(c[1]), "+f"(c[2]), "+f"(c[3])
        : "r"(a[0]), "r"(a[1]), "r"(a[2]), "r"(a[3]), "r"(b[0]), "r"(b[1]));
}
// split two fp32 into packed bf16x2 hi + lo
__device__ __forceinline__ void split2(float a, float b, uint32_t& hi, uint32_t& lo) {
    __nv_bfloat162 h = __floats2bfloat162_rn(a, b);
    float ra = a - __bfloat162float(h.x);
    float rb = b - __bfloat162float(h.y);
    __nv_bfloat162 l = __floats2bfloat162_rn(ra, rb);
    memcpy(&hi, &h, 4);
    memcpy(&lo, &l, 4);
}
__device__ __forceinline__ uint32_t pack2(float a, float b) {
    __nv_bfloat162 h = __floats2bfloat162_rn(a, b);
    uint32_t u; memcpy(&u, &h, 4); return u;
}

// ============================================================================
// split fp32 -> (hi, lo) bf16, elementwise. n % 4 == 0.
// ============================================================================
__global__ __launch_bounds__(256)
void split_kernel(const float* __restrict__ in,
                  __nv_bfloat16* __restrict__ hi,
                  __nv_bfloat16* __restrict__ lo, int n)
{
    int i = (blockIdx.x * 256 + threadIdx.x) * 4;
    if (i >= n) return;
    float4 v = *(const float4*)(in + i);
    uint32_t h0, l0, h1, l1;
    split2(v.x, v.y, h0, l0);
    split2(v.z, v.w, h1, l1);
    ((uint32_t*)(hi + i))[0] = h0;
    ((uint32_t*)(hi + i))[1] = h1;
    ((uint32_t*)(lo + i))[0] = l0;
    ((uint32_t*)(lo + i))[1] = l1;
}

// ============================================================================
// transpose + split: W fp32 [K,N] -> hi/lo bf16 [N,K].  K,N % 32 == 0.
// ============================================================================
__global__ __launch_bounds__(256)
void tsplit_kernel(const float* __restrict__ W,
                   __nv_bfloat16* __restrict__ ht,
                   __nv_bfloat16* __restrict__ lt, int K, int N)
{
    __shared__ float tile[32][33];
    const int k0 = blockIdx.y * 32, n0 = blockIdx.x * 32;
    const int tx = threadIdx.x & 31, ty = threadIdx.x >> 5;
    for (int r = ty; r < 32; r += 8)
        tile[r][tx] = W[(size_t)(k0 + r) * N + n0 + tx];
    __syncthreads();
    for (int r = ty; r < 32; r += 8) {
        float v = tile[tx][r];
        __nv_bfloat16 h = __float2bfloat16_rn(v);
        __nv_bfloat16 l = __float2bfloat16_rn(v - __bfloat162float(h));
        ht[(size_t)(n0 + r) * K + k0 + tx] = h;
        lt[(size_t)(n0 + r) * K + k0 + tx] = l;
    }
}

// ============================================================================
// transpose V: [b, skv, h*64+d] hi/lo -> [(b*16+h)*64+d][skv] hi/lo
// ============================================================================
__global__ __launch_bounds__(256)
void vtrans_kernel(const __nv_bfloat16* __restrict__ Vh,
                   const __nv_bfloat16* __restrict__ Vl,
                   __nv_bfloat16* __restrict__ Vth,
                   __nv_bfloat16* __restrict__ Vtl)
{
    __shared__ __nv_bfloat16 th[32][33], tl[32][33];
    const int bh = blockIdx.z;
    const int b = bh >> 4, h = bh & 15;
    const int kv0 = blockIdx.x * 32, d0 = blockIdx.y * 32;
    const int tx = threadIdx.x & 31, ty = threadIdx.x >> 5;
    for (int r = ty; r < 32; r += 8) {
        const size_t src = ((size_t)(b * SKV_) + kv0 + r) * INNER_ + h * 64 + d0 + tx;
        th[r][tx] = Vh[src];
        tl[r][tx] = Vl[src];
    }
    __syncthreads();
    for (int r = ty; r < 32; r += 8) {
        const size_t dst = ((size_t)bh * 64 + d0 + r) * SKV_ + kv0 + tx;
        Vth[dst] = th[tx][r];
        Vtl[dst] = tl[tx][r];
    }
}

// ============================================================================
// HMMA GEMM: C = (Ah+Al)[M,K] @ (Bh+Bl)^T.
//   SPLIT=false: fp32 out + bias.  SPLIT=true: bf16 hi/lo out.
//   BM=BN=128, BK=32, 4-stage cp.async, 256 threads, 8 warps (4m x 2n).
// ============================================================================
#define MM_BM 128
#define MM_BN 128
#define MM_BK 32
#define MM_ROWB 80
#define MM_AB  (128 * MM_ROWB)
#define MM_STAGE (2 * MM_AB)
#define MM_SMEM (4 * MM_STAGE)

template<bool SPLIT>
__global__ __launch_bounds__(256)
void gemm_mma(const __nv_bfloat16* __restrict__ Ah,
              const __nv_bfloat16* __restrict__ Al,
              const __nv_bfloat16* __restrict__ Bh,
              const __nv_bfloat16* __restrict__ Bl,
              const float* __restrict__ bias,
              float* __restrict__ C,
              __nv_bfloat16* __restrict__ Ch,
              __nv_bfloat16* __restrict__ Cl,
              int M, int N, int K)
{
    extern __shared__ __align__(16) char smem_raw[];
    const uint32_t sbase = smem_u32(smem_raw);

    const int tid  = threadIdx.x;
    const int wid  = tid >> 5, lane = tid & 31;
    const int wm   = wid >> 1, wn = wid & 1;
    const int m0   = blockIdx.y * MM_BM;
    const int n0   = blockIdx.x * MM_BN;

    const __nv_bfloat16* Asegs[3] = {Ah, Al, Ah};
    const __nv_bfloat16* Bsegs[3] = {Bh, Bh, Bl};
    const int kiters = K / MM_BK;
    const int T = 3 * kiters;

    auto load_stage = [&](int t, int s) {
        const int seg = t / kiters;
        const int kk  = (t - seg * kiters) * MM_BK;
        const __nv_bfloat16* Ap = Asegs[seg];
        const __nv_bfloat16* Bp = Bsegs[seg];
        const uint32_t sa = sbase + (uint32_t)s * MM_STAGE;
        const uint32_t sb = sa + MM_AB;
        #pragma unroll
        for (int i = 0; i < 2; i++) {
            const int idx = i * 256 + tid;
            const int r = idx >> 2, c = idx & 3;
            cp_async16(sa + r * MM_ROWB + c * 16,
                       Ap + (size_t)(m0 + r) * K + kk + c * 8);
            cp_async16(sb + r * MM_ROWB + c * 16,
                       Bp + (size_t)(n0 + r) * K + kk + c * 8);
        }
        cp_commit();
    };

    float acc[2][8][4];
    #pragma unroll
    for (int mi = 0; mi < 2; mi++)
        #pragma unroll
        for (int nj = 0; nj < 8; nj++)
            #pragma unroll
            for (int q = 0; q < 4; q++) acc[mi][nj][q] = 0.f;

    load_stage(0, 0);
    load_stage(1, 1);
    load_stage(2, 2);

    const uint32_t aRow = (uint32_t)(wm * 32 + (lane & 15));
    const uint32_t aKof = ((lane >> 4) << 4);
    const uint32_t bRow = (uint32_t)(wn * 64 + ((lane >> 4) & 1) * 8 + (lane & 7));
    const uint32_t bKof = (((lane >> 3) & 1) << 4);

    for (int t = 0; t < T; t++) {
        const int s = t & 3;
        cp_wait<2>();
        __syncthreads();

        const uint32_t sa = sbase + (uint32_t)s * MM_STAGE;
        const uint32_t sb = sa + MM_AB;

        #pragma unroll
        for (int ks = 0; ks < 2; ks++) {
            uint32_t a[2][4], b[8][2];
            #pragma unroll
            for (int mi = 0; mi < 2; mi++) {
                const uint32_t addr =
                    sa + (aRow + mi * 16) * MM_ROWB + ks * 32 + aKof;
                ldmatrix_x4(a[mi][0], a[mi][1], a[mi][2], a[mi][3], addr);
            }
            #pragma unroll
            for (int nj = 0; nj < 8; nj += 2) {
                const uint32_t addr =
                    sb + (bRow + nj * 8) * MM_ROWB + ks * 32 + bKof;
                ldmatrix_x4(b[nj][0], b[nj][1], b[nj + 1][0], b[nj + 1][1], addr);
            }
            #pragma unroll
            for (int mi = 0; mi < 2; mi++)
                #pragma unroll
                for (int nj = 0; nj < 8; nj++)
                    mma_bf16(acc[mi][nj], a[mi], b[nj]);
        }

        __syncthreads();
        if (t + 3 < T) load_stage(t + 3, (t + 3) & 3);
        else           cp_commit();
    }

    #pragma unroll
    for (int mi = 0; mi < 2; mi++) {
        const int row = m0 + wm * 32 + mi * 16 + (lane >> 2);
        #pragma unroll
        for (int nj = 0; nj < 8; nj++) {
            const int col = n0 + wn * 64 + nj * 8 + 2 * (lane & 3);
            if (SPLIT) {
                uint32_t h0, l0, h1, l1;
                split2(acc[mi][nj][0], acc[mi][nj][1], h0, l0);
                split2(acc[mi][nj][2], acc[mi][nj][3], h1, l1);
                *(uint32_t*)(Ch + (size_t)row * N + col)       = h0;
                *(uint32_t*)(Cl + (size_t)row * N + col)       = l0;
                *(uint32_t*)(Ch + (size_t)(row + 8) * N + col) = h1;
                *(uint32_t*)(Cl + (size_t)(row + 8) * N + col) = l1;
            } else {
                const float b0 = bias[col], b1 = bias[col + 1];
                float2 v0 = make_float2(acc[mi][nj][0] + b0, acc[mi][nj][1] + b1);
                float2 v1 = make_float2(acc[mi][nj][2] + b0, acc[mi][nj][3] + b1);
                *(float2*)(C + (size_t)row * N + col)       = v0;
                *(float2*)(C + (size_t)(row + 8) * N + col) = v1;
            }
        }
    }
}

// ============================================================================
// HMMA flash attention.
//   CTA: 128 q rows x one (b,h). 8 warps, each 16 q rows x full 128-kv tile.
//   S = Qh.Kh + Ql.Kh + Qh.Kl ; online softmax fp32 ; PV = Ph.Vh + Pl.Vh + Ph.Vl
//   K tile in smem as [kv][64] rows (like GEMM B). V pre-transposed [d][kv].
//   Output: bf16 hi/lo.
// ============================================================================
#define AT_QROWB 144                     // 64 bf16 = 128B + 16 pad
#define AT_VROWB 272                     // 128 bf16 = 256B + 16 pad
#define AT_QSZ   (128 * AT_QROWB)        // 18432 per matrix
#define AT_KSZ   (128 * AT_QROWB)        // 18432
#define AT_VSZ   (64 * AT_VROWB)         // 17408
#define AT_STAGE (2 * AT_KSZ + 2 * AT_VSZ)   // 71680
#define AT_SMEM  (2 * AT_QSZ + 2 * AT_STAGE) // 180224

__global__ __launch_bounds__(256, 1)
void attn_mma(const __nv_bfloat16* __restrict__ Qh,
              const __nv_bfloat16* __restrict__ Ql,
              const __nv_bfloat16* __restrict__ Kh,
              const __nv_bfloat16* __restrict__ Kl,
              const __nv_bfloat16* __restrict__ Vth,
              const __nv_bfloat16* __restrict__ Vtl,
              __nv_bfloat16* __restrict__ AOh,
              __nv_bfloat16* __restrict__ AOl)
{
    extern __shared__ __align__(16) char smem_raw[];
    const uint32_t sbase = smem_u32(smem_raw);
    const uint32_t SQHo = sbase;
    const uint32_t SQLo = sbase + AT_QSZ;

    const int tid  = threadIdx.x;
    const int wid  = tid >> 5, lane = tid & 31;
    const int bh = blockIdx.y;
    const int b = bh >> 4, h = bh & 15;
    const int q0 = blockIdx.x * 128;

    // ---- loaders ----
    auto load_q = [&]() {
        #pragma unroll
        for (int it = 0; it < 8; it++) {
            const int idx = it * 256 + tid;       // 0..2047
            const int arr = idx >> 10, rem = idx & 1023;
            const int r = rem >> 3, c = rem & 7;
            const __nv_bfloat16* src = (arr ? Ql : Qh) +
                ((size_t)(b * SQ_) + q0 + r) * INNER_ + h * 64 + c * 8;
            cp_async16((arr ? SQLo : SQHo) + r * AT_QROWB + c * 16, src);
        }
        cp_commit();
    };
    auto load_kv = [&](int iter, int s) {
        const int kv0 = iter * 128;
        const uint32_t sk = sbase + 2 * AT_QSZ + (uint32_t)s * AT_STAGE;
        const uint32_t sv = sk + 2 * AT_KSZ;
        #pragma unroll
        for (int it = 0; it < 8; it++) {
            const int idx = it * 256 + tid;       // 0..2047
            const int arr = idx >> 10, rem = idx & 1023;
            const int r = rem >> 3, c = rem & 7;
            const __nv_bfloat16* src = (arr ? Kl : Kh) +
                ((size_t)(b * SKV_) + kv0 + r) * INNER_ + h * 64 + c * 8;
            cp_async16(sk + arr * AT_KSZ + r * AT_QROWB + c * 16, src);
        }
        #pragma unroll
        for (int it = 0; it < 8; it++) {
            const int idx = it * 256 + tid;       // 0..2047
            const int arr = idx >> 10, rem = idx & 1023;
            const int r = rem >> 4, c = rem & 15;  // r 0..63, c 0..15
            const __nv_bfloat16* src = (arr ? Vtl : Vth) +
                ((size_t)bh * 64 + r) * SKV_ + kv0 + c * 8;
            cp_async16(sv + arr * AT_VSZ + r * AT_VROWB + c * 16, src);
        }
        cp_commit();
    };

    load_q();
    load_kv(0, 0);
    load_kv(1, 1);

    // ldmatrix addressing (identical pattern to gemm_mma, validated)
    const uint32_t aRow = (uint32_t)(wid * 16 + (lane & 15));
    const uint32_t aKof = ((lane >> 4) << 4);
    const uint32_t bRow = (uint32_t)(((lane >> 4) & 1) * 8 + (lane & 7));
    const uint32_t bKof = (((lane >> 3) & 1) << 4);

    // Q fragments (persistent across kv loop)
    uint32_t qfh[4][4], qfl[4][4];
    cp_wait<2>();          // Q group retired (groups retire in order)
    __syncthreads();
    #pragma unroll
    for (int kt = 0; kt < 4; kt++) {
        ldmatrix_x4(qfh[kt][0], qfh[kt][1], qfh[kt][2], qfh[kt][3],
                    SQHo + aRow * AT_QROWB + kt * 32 + aKof);
        ldmatrix_x4(qfl[kt][0], qfl[kt][1], qfl[kt][2], qfl[kt][3],
                    SQLo + aRow * AT_QROWB + kt * 32 + aKof);
    }

    float pv[8][4];
    #pragma unroll
    for (int t = 0; t < 8; t++)
        #pragma unroll
        for (int q = 0; q < 4; q++) pv[t][q] = 0.f;
    float m0 = -1e30f, m1 = -1e30f, l0 = 0.f, l1 = 0.f;
    const float scale = 0.125f;
    const unsigned FULL = 0xffffffffu;

    for (int iter = 0; iter < SKV_ / 128; iter++) {
        const int s = iter & 1;
        cp_wait<1>();
        __syncthreads();
        const uint32_t sk = sbase + 2 * AT_QSZ + (uint32_t)s * AT_STAGE;
        const uint32_t sv = sk + 2 * AT_KSZ;

        // ---- S = Q @ K^T (3-term split), 16 q x 128 kv per warp ----
        float sacc[16][4];
        #pragma unroll
        for (int nj = 0; nj < 16; nj++)
            #pragma unroll
            for (int q = 0; q < 4; q++) sacc[nj][q] = 0.f;

        #pragma unroll
        for (int kt = 0; kt < 4; kt++) {
            uint32_t bk[16][2];
            #pragma unroll
            for (int njp = 0; njp < 8; njp++)
                ldmatrix_x4(bk[2 * njp][0], bk[2 * njp][1],
                            bk[2 * njp + 1][0], bk[2 * njp + 1][1],
                            sk + (bRow + njp * 16) * AT_QROWB + kt * 32 + bKof);
            #pragma unroll
            for (int nj = 0; nj < 16; nj++) {
                mma_bf16(sacc[nj], qfh[kt], bk[nj]);
                mma_bf16(sacc[nj], qfl[kt], bk[nj]);
            }
            #pragma unroll
            for (int njp = 0; njp < 8; njp++)
                ldmatrix_x4(bk[2 * njp][0], bk[2 * njp][1],
                            bk[2 * njp + 1][0], bk[2 * njp + 1][1],
                            sk + AT_KSZ + (bRow + njp * 16) * AT_QROWB + kt * 32 + bKof);
            #pragma unroll
            for (int nj = 0; nj < 16; nj++)
                mma_bf16(sacc[nj], qfh[kt], bk[nj]);
        }

        // ---- online softmax (rows r0 = lane>>2, r1 = r0+8) ----
        float mt0 = -1e30f, mt1 = -1e30f;
        #pragma unroll
        for (int nj = 0; nj < 16; nj++) {
            sacc[nj][0] *= scale; sacc[nj][1] *= scale;
            sacc[nj][2] *= scale; sacc[nj][3] *= scale;
            mt0 = fmaxf(mt0, fmaxf(sacc[nj][0], sacc[nj][1]));
            mt1 = fmaxf(mt1, fmaxf(sacc[nj][2], sacc[nj][3]));
        }
        mt0 = fmaxf(mt0, __shfl_xor_sync(FULL, mt0, 1));
        mt0 = fmaxf(mt0, __shfl_xor_sync(FULL, mt0, 2));
        mt1 = fmaxf(mt1, __shfl_xor_sync(FULL, mt1, 1));
        mt1 = fmaxf(mt1, __shfl_xor_sync(FULL, mt1, 2));

        const float mn0 = fmaxf(m0, mt0), mn1 = fmaxf(m1, mt1);
        const float c0 = __expf(m0 - mn0), c1 = __expf(m1 - mn1);
        float s0 = 0.f, s1 = 0.f;
        #pragma unroll
        for (int nj = 0; nj < 16; nj++) {
            float p0 = __expf(sacc[nj][0] - mn0);
            float p1 = __expf(sacc[nj][1] - mn0);
            float p2 = __expf(sacc[nj][2] - mn1);
            float p3 = __expf(sacc[nj][3] - mn1);
            sacc[nj][0] = p0; sacc[nj][1] = p1;
            sacc[nj][2] = p2; sacc[nj][3] = p3;
            s0 += p0 + p1; s1 += p2 + p3;
        }
        s0 += __shfl_xor_sync(FULL, s0, 1); s0 += __shfl_xor_sync(FULL, s0, 2);
        s1 += __shfl_xor_sync(FULL, s1, 1); s1 += __shfl_xor_sync(FULL, s1, 2);
        l0 = l0 * c0 + s0; m0 = mn0;
        l1 = l1 * c1 + s1; m1 = mn1;
        #pragma unroll
        for (int t = 0; t < 8; t++) {
            pv[t][0] *= c0; pv[t][1] *= c0;
            pv[t][2] *= c1; pv[t][3] *= c1;
        }

        // ---- PV: repack C->A fragments, 3-term split ----
        #pragma unroll
        for (int j = 0; j < 8; j++) {
            uint32_t ph[4], pl[4];
            split2(sacc[2 * j][0],     sacc[2 * j][1],     ph[0], pl[0]);
            split2(sacc[2 * j][2],     sacc[2 * j][3],     ph[1], pl[1]);
            split2(sacc[2 * j + 1][0], sacc[2 * j + 1][1], ph[2], pl[2]);
            split2(sacc[2 * j + 1][2], sacc[2 * j + 1][3], ph[3], pl[3]);
            #pragma unroll
            for (int tp = 0; tp < 4; tp++) {
                uint32_t bv[2][2];
                ldmatrix_x4(bv[0][0], bv[0][1], bv[1][0], bv[1][1],
                            sv + (bRow + tp * 16) * AT_VROWB + j * 32 + bKof);
                mma_bf16(pv[2 * tp],     ph, bv[0]);
                mma_bf16(pv[2 * tp + 1], ph, bv[1]);
                mma_bf16(pv[2 * tp],     pl, bv[0]);
                mma_bf16(pv[2 * tp + 1], pl, bv[1]);
                ldmatrix_x4(bv[0][0], bv[0][1], bv[1][0], bv[1][1],
                            sv + AT_VSZ + (bRow + tp * 16) * AT_VROWB + j * 32 + bKof);
                mma_bf16(pv[2 * tp],     ph, bv[0]);
                mma_bf16(pv[2 * tp + 1], ph, bv[1]);
            }
        }

        __syncthreads();
        if (iter + 2 < SKV_ / 128) load_kv(iter + 2, s);
    }

    // ---- epilogue: normalize + bf16 split out ----
    const float inv0 = 1.0f / l0, inv1 = 1.0f / l1;
    const int r0g = q0 + wid * 16 + (lane >> 2);
    const size_t base0 = ((size_t)(b * SQ_) + r0g) * INNER_ + h * 64;
    const size_t base1 = base0 + (size_t)8 * INNER_;
    #pragma unroll
    for (int t = 0; t < 8; t++) {
        const int col = t * 8 + 2 * (lane & 3);
        uint32_t h0, lo0, h1, lo1;
        split2(pv[t][0] * inv0, pv[t][1] * inv0, h0, lo0);
        split2(pv[t][2] * inv1, pv[t][3] * inv1, h1, lo1);
        *(uint32_t*)(AOh + base0 + col) = h0;
        *(uint32_t*)(AOl + base0 + col) = lo0;
        *(uint32_t*)(AOh + base1 + col) = h1;
        *(uint32_t*)(AOl + base1 + col) = lo1;
    }
}

// ============================================================================
// launch
// ============================================================================
extern "C" void kernel_launch(void* const* d_in, const int* in_sizes, int n_in,
                              void* d_out, int out_size)
{
    const float* x   = (const float*)d_in[0];
    const float* ctx = (const float*)d_in[1];
    const float* Wq  = (const float*)d_in[2];
    const float* Wk  = (const float*)d_in[3];
    const float* Wv  = (const float*)d_in[4];
    const float* Wo  = (const float*)d_in[5];
    const float* bo  = (const float*)d_in[6];
    float* out = (float*)d_out;

    __nv_bfloat16 *xh, *xl, *ch, *cl, *aoh, *aol;
    __nv_bfloat16 *qh, *ql, *kh, *kl, *vh, *vl, *vth, *vtl;
    __nv_bfloat16 *wqh, *wql, *wkh, *wkl, *wvh, *wvl, *woh, *wol;
    cudaGetSymbolAddress((void**)&xh,  g_xh);   cudaGetSymbolAddress((void**)&xl,  g_xl);
    cudaGetSymbolAddress((void**)&ch,  g_ch);   cudaGetSymbolAddress((void**)&cl,  g_cl);
    cudaGetSymbolAddress((void**)&aoh, g_aoh);  cudaGetSymbolAddress((void**)&aol, g_aol);
    cudaGetSymbolAddress((void**)&qh,  g_Qh);   cudaGetSymbolAddress((void**)&ql,  g_Ql);
    cudaGetSymbolAddress((void**)&kh,  g_Kh);   cudaGetSymbolAddress((void**)&kl,  g_Kl);
    cudaGetSymbolAddress((void**)&vh,  g_Vh);   cudaGetSymbolAddress((void**)&vl,  g_Vl);
    cudaGetSymbolAddress((void**)&vth, g_Vth);  cudaGetSymbolAddress((void**)&vtl, g_Vtl);
    cudaGetSymbolAddress((void**)&wqh, g_Wqh);  cudaGetSymbolAddress((void**)&wql, g_Wql);
    cudaGetSymbolAddress((void**)&wkh, g_Wkh);  cudaGetSymbolAddress((void**)&wkl, g_Wkl);
    cudaGetSymbolAddress((void**)&wvh, g_Wvh);  cudaGetSymbolAddress((void**)&wvl, g_Wvl);
    cudaGetSymbolAddress((void**)&woh, g_Woh);  cudaGetSymbolAddress((void**)&wol, g_Wol);

    const int nx = B_ * SQ_  * QDIM_;
    const int nc = B_ * SKV_ * CDIM_;

    split_kernel<<<nx / 1024, 256>>>(x,   xh, xl, nx);
    split_kernel<<<nc / 1024, 256>>>(ctx, ch, cl, nc);
    tsplit_kernel<<<dim3(INNER_ / 32, QDIM_ / 32), 256>>>(Wq, wqh, wql, QDIM_, INNER_);
    tsplit_kernel<<<dim3(INNER_ / 32, CDIM_ / 32), 256>>>(Wk, wkh, wkl, CDIM_, INNER_);
    tsplit_kernel<<<dim3(INNER_ / 32, CDIM_ / 32), 256>>>(Wv, wvh, wvl, CDIM_, INNER_);
    tsplit_kernel<<<dim3(QDIM_  / 32, INNER_ / 32), 256>>>(Wo, woh, wol, INNER_, QDIM_);

    cudaFuncSetAttribute(gemm_mma<false>,
                         cudaFuncAttributeMaxDynamicSharedMemorySize, MM_SMEM);
    cudaFuncSetAttribute(gemm_mma<true>,
                         cudaFuncAttributeMaxDynamicSharedMemorySize, MM_SMEM);
    cudaFuncSetAttribute(attn_mma,
                         cudaFuncAttributeMaxDynamicSharedMemorySize, AT_SMEM);

    // projections -> bf16 hi/lo directly
    gemm_mma<true><<<dim3(INNER_ / MM_BN, (B_ * SQ_)  / MM_BM), 256, MM_SMEM>>>(
        xh, xl, wqh, wql, nullptr, nullptr, qh, ql, B_ * SQ_,  INNER_, QDIM_);
    gemm_mma<true><<<dim3(INNER_ / MM_BN, (B_ * SKV_) / MM_BM), 256, MM_SMEM>>>(
        ch, cl, wkh, wkl, nullptr, nullptr, kh, kl, B_ * SKV_, INNER_, CDIM_);
    gemm_mma<true><<<dim3(INNER_ / MM_BN, (B_ * SKV_) / MM_BM), 256, MM_SMEM>>>(
        ch, cl, wvh, wvl, nullptr, nullptr, vh, vl, B_ * SKV_, INNER_, CDIM_);

    vtrans_kernel<<<dim3(SKV_ / 32, 2, BH_), 256>>>(vh, vl, vth, vtl);

    attn_mma<<<dim3(SQ_ / 128, BH_), 256, AT_SMEM>>>(
        qh, ql, kh, kl, vth, vtl, aoh, aol);

    gemm_mma<false><<<dim3(QDIM_ / MM_BN, (B_ * SQ_) / MM_BM), 256, MM_SMEM>>>(
        aoh, aol, woh, wol, bo, out, nullptr, nullptr, B_ * SQ_, QDIM_, INNER_);
}